// round 15
// baseline (speedup 1.0000x reference)
#include <cuda_runtime.h>
#include <cuda_bf16.h>
#include <cstdint>
#include <math.h>

typedef unsigned int u32;

#define BB 8
#define NNODE 1024
#define FD 128
#define GD 64
#define EC 2
#define NH 4
#define NEDGE 16384
#define L0D 256
#define ROWS (BB*NNODE)
#define ECAP 64
#define NSTAGE 4

// ---------------- scratch ----------------
__device__ u32 g_deg[16*1024];
__device__ unsigned short g_edges2[16*1024*ECAP];
__device__ __align__(4) __nv_bfloat16 g_Whb[(size_t)ROWS*512];
__device__ float g_qv[ROWS*16];
__device__ float g_W2[512*128];
__device__ float g_Xsum[BB*FD];
__device__ float g_Swh[BB*512];
__device__ float g_T1[ROWS*FD];
__device__ float g_U[ROWS*L0D];
__device__ float g_T3[ROWS*FD];
__device__ float g_stats[1024];
// split-bf16 A matrices [Ahi | Ahi | Alo] along K, tile-chunk-contiguous swizzled layout
__device__ __align__(16) __nv_bfloat16 g_A0[(size_t)ROWS*384];
__device__ __align__(16) __nv_bfloat16 g_A1[(size_t)ROWS*1536];
__device__ __align__(16) __nv_bfloat16 g_A2[(size_t)ROWS*384];
__device__ __align__(16) __nv_bfloat16 g_A3[(size_t)ROWS*768];
// split-bf16 B matrices [Bhi | Blo | Bhi] along K, same tiled layout ("row" = output col)
__device__ __align__(16) __nv_bfloat16 g_B0[640*384];
__device__ __align__(16) __nv_bfloat16 g_B1[128*1536];
__device__ __align__(16) __nv_bfloat16 g_B2[256*384];
__device__ __align__(16) __nv_bfloat16 g_B3[128*768];

// tiled index: tile = row>>6, chunk = k>>5; within tile: 64 rows x 32 halves,
// 16B part swizzled by p ^ ((r>>1)&3) for conflict-free ldmatrix
__device__ __forceinline__ size_t tidx(int row, int k, int nkc) {
    int rt = row >> 6;
    int r = row & 63;
    int ch = k >> 5;
    int kc = k & 31;
    int ps = (kc >> 3) ^ ((r >> 1) & 3);
    return ((size_t)(rt * nkc + ch) * 64 + r) * 32 + ps * 8 + (kc & 7);
}

// ---------------- asm helpers ----------------
__device__ __forceinline__ void cpbulk(u32 dst, const void* src, u32 bytes, u32 mbar) {
    asm volatile("cp.async.bulk.shared::cluster.global.mbarrier::complete_tx::bytes [%0], [%1], %2, [%3];\n"
                 :: "r"(dst), "l"(src), "r"(bytes), "r"(mbar) : "memory");
}
__device__ __forceinline__ void mbar_init(u32 mbar, u32 cnt) {
    asm volatile("mbarrier.init.shared.b64 [%0], %1;\n" :: "r"(mbar), "r"(cnt) : "memory");
}
__device__ __forceinline__ void mbar_expect(u32 mbar, u32 bytes) {
    asm volatile("mbarrier.arrive.expect_tx.shared.b64 _, [%0], %1;\n" :: "r"(mbar), "r"(bytes) : "memory");
}
__device__ __forceinline__ void mbar_wait(u32 mbar, u32 parity) {
    asm volatile(
        "{\n\t"
        ".reg .pred P1;\n\t"
        "WAIT_LOOP_%=:\n\t"
        "mbarrier.try_wait.parity.acquire.cta.shared::cta.b64 P1, [%0], %1, 0x989680;\n\t"
        "@P1 bra.uni WAIT_DONE_%=;\n\t"
        "bra.uni WAIT_LOOP_%=;\n\t"
        "WAIT_DONE_%=:\n\t"
        "}"
        :: "r"(mbar), "r"(parity) : "memory");
}
__device__ __forceinline__ void ldsm4(u32& r0, u32& r1, u32& r2, u32& r3, u32 a) {
    asm volatile("ldmatrix.sync.aligned.m8n8.x4.shared.b16 {%0,%1,%2,%3}, [%4];\n"
                 : "=r"(r0), "=r"(r1), "=r"(r2), "=r"(r3) : "r"(a));
}
__device__ __forceinline__ void mma16816(float* d, const u32* a, const u32* b) {
    asm volatile("mma.sync.aligned.m16n8k16.row.col.f32.bf16.bf16.f32 "
                 "{%0,%1,%2,%3},{%4,%5,%6,%7},{%8,%9},{%0,%1,%2,%3};\n"
                 : "+f"(d[0]), "+f"(d[1]), "+f"(d[2]), "+f"(d[3])
                 : "r"(a[0]), "r"(a[1]), "r"(a[2]), "r"(a[3]), "r"(b[0]), "r"(b[1]));
}
__device__ __forceinline__ void split2(float x, __nv_bfloat16& hi, __nv_bfloat16& lo) {
    hi = __float2bfloat16(x);
    lo = __float2bfloat16(x - __bfloat162float(hi));
}

// ---------------- weight packing + all zero-init ----------------
__global__ void k_packb(const float* __restrict__ Ws, const float* __restrict__ Wemb,
                        const float* __restrict__ Wl0, const float* __restrict__ Wl1,
                        const float* __restrict__ Wq, const float* __restrict__ Wv) {
    int idx = blockIdx.x * blockDim.x + threadIdx.x;
    __nv_bfloat16 hi, lo;
    if (idx < 65536) {                       // B0 main: cols 0..511, K3=384 (nkc 12)
        int col = idx >> 7;
        int f = idx & 127;
        int e = col >> 8;
        int rem = col & 255;
        int h = rem >> 6;
        int g = rem & 63;
        split2(Ws[((size_t)e * 512 + h * 128 + f) * GD + g], hi, lo);
        g_B0[tidx(col, f, 12)] = hi;
        g_B0[tidx(col, 128 + f, 12)] = lo;
        g_B0[tidx(col, 256 + f, 12)] = hi;
    } else if (idx < 131072) {               // B1: 128 cols, K3=1536 (nkc 48)
        int i2 = idx - 65536;
        int col = i2 >> 9;
        int k = i2 & 511;
        split2(Wemb[col * 512 + k], hi, lo);
        g_B1[tidx(col, k, 48)] = hi;
        g_B1[tidx(col, 512 + k, 48)] = lo;
        g_B1[tidx(col, 1024 + k, 48)] = hi;
    } else if (idx < 163840) {               // B2: 256 cols, K3=384 (nkc 12)
        int i2 = idx - 131072;
        int col = i2 >> 7;
        int k = i2 & 127;
        split2(Wl0[col * 128 + k], hi, lo);
        g_B2[tidx(col, k, 12)] = hi;
        g_B2[tidx(col, 128 + k, 12)] = lo;
        g_B2[tidx(col, 256 + k, 12)] = hi;
    } else if (idx < 196608) {               // B3: 128 cols, K3=768 (nkc 24)
        int i2 = idx - 163840;
        int col = i2 >> 8;
        int k = i2 & 255;
        split2(Wl1[col * 256 + k], hi, lo);
        g_B3[tidx(col, k, 24)] = hi;
        g_B3[tidx(col, 256 + k, 24)] = lo;
        g_B3[tidx(col, 512 + k, 24)] = hi;
    } else if (idx < 198656) {               // B0 qv rows: cols 512..527
        int i2 = idx - 196608;
        int j = i2 >> 7;
        int f = i2 & 127;
        int col = 512 + j;
        float w;
        if (j < 8) w = Wq[(j >> 2) * 512 + (j & 3) * 128 + f];
        else {
            int c = j - 8;
            w = Wv[(c >> 2) * 512 + (c & 3) * 128 + f];
        }
        split2(w, hi, lo);
        g_B0[tidx(col, f, 12)] = hi;
        g_B0[tidx(col, 128 + f, 12)] = lo;
        g_B0[tidx(col, 256 + f, 12)] = hi;
    } else if (idx < 264192) {               // W2 fp32: 512 x 128 (for Swh)
        int i2 = idx - 198656;
        int col = i2 >> 7;
        int f = i2 & 127;
        int e = col >> 8;
        int rem = col & 255;
        int h = rem >> 6;
        int g = rem & 63;
        g_W2[i2] = Ws[((size_t)e * 512 + h * 128 + f) * GD + g];
    } else if (idx < 280576) {               // zero g_deg
        g_deg[idx - 264192] = 0u;
    } else if (idx < 281600) {               // zero g_stats
        g_stats[idx - 280576] = 0.f;
    } else if (idx < 282624) {               // zero g_Xsum
        g_Xsum[idx - 281600] = 0.f;
    }
}

// ---------------- edge buckets ----------------
__global__ void k_bucket(const int* __restrict__ A) {
    int idx = blockIdx.x * blockDim.x + threadIdx.x;
    int be = idx >> 14;
    int i = idx & (NEDGE - 1);
    int src = A[(be * 2 + 0) * NEDGE + i];
    int dst = A[(be * 2 + 1) * NEDGE + i];
    int row = be * 1024 + src;
    u32 pos = atomicAdd(&g_deg[row], 1u);
    if (pos < ECAP) g_edges2[(size_t)row * ECAP + pos] = (unsigned short)dst;
}

// X -> A0 split (tiled) + per-batch column sums
__global__ __launch_bounds__(256) void k_conv0(const float* __restrict__ X) {
    __shared__ float sh[256];
    int t = threadIdx.x;
    int row0 = blockIdx.x * 16;
    int b = row0 >> 10;
    int f = t & 127;
    int rl = t >> 7;
    float s = 0.f;
    for (int r = rl; r < 16; r += 2) {
        int row = row0 + r;
        float x = X[(size_t)row * FD + f];
        s += x;
        __nv_bfloat16 hi, lo;
        split2(x, hi, lo);
        g_A0[tidx(row, f, 12)] = hi;
        g_A0[tidx(row, 128 + f, 12)] = hi;
        g_A0[tidx(row, 256 + f, 12)] = lo;
    }
    sh[t] = s;
    __syncthreads();
    if (t < 128) atomicAdd(&g_Xsum[b * FD + t], sh[t] + sh[t + 128]);
}

// bn conversions: PH2 bn(T1)->A2 (nkc 12), PH3 elu(bn(U))->A3 (nkc 24)
template <int PH>
__global__ void k_conv() {
    constexpr int C = (PH == 3) ? 256 : 128;
    constexpr int NKC = (PH == 3) ? 24 : 12;
    int idx = blockIdx.x * blockDim.x + threadIdx.x;
    int row = idx / C;
    int k = idx % C;
    constexpr int SO = (PH == 2) ? 0 : 256;
    constexpr int QO = (PH == 2) ? 128 : 512;
    const float* src = (PH == 2) ? g_T1 : g_U;
    float mu = g_stats[SO + k] * (1.f / 8192.f);
    float var = g_stats[QO + k] * (1.f / 8192.f) - mu * mu;
    float x = (src[idx] - mu) * rsqrtf(var + 1e-5f);
    if (PH == 3) x = x > 0.f ? x : expm1f(x);
    __nv_bfloat16 hi, lo;
    split2(x, hi, lo);
    __nv_bfloat16* a = (PH == 2) ? g_A2 : g_A3;
    a[tidx(row, k, NKC)] = hi;
    a[tidx(row, C + k, NKC)] = hi;
    a[tidx(row, 2 * C + k, NKC)] = lo;
}

// Swh[b][col] = sum_f Xsum[b][f] * W2[col][f]
__global__ void k_swh() {
    __shared__ float sx[128];
    int b = blockIdx.x;
    int col = blockIdx.y * 128 + threadIdx.x;
    if (threadIdx.x < 128) sx[threadIdx.x] = g_Xsum[b * FD + threadIdx.x];
    __syncthreads();
    float s = 0.f;
#pragma unroll 4
    for (int f = 0; f < 128; f++) s += sx[f] * g_W2[col * 128 + f];
    g_Swh[b * 512 + col] = s;
}

// ---------------- tensor-core GEMM: 64x(64|128) tiles, bulk-copy pipeline ----------------
// WN = per-warp N width: 64 for PH0/PH2 (wide outputs), 32 for PH1/PH3
template <int PH>
__global__ __launch_bounds__(128) void k_mma(const float* __restrict__ ext_x) {
    constexpr int K3 = (PH == 0) ? 384 : (PH == 1) ? 1536 : (PH == 2) ? 384 : 768;
    constexpr int NC = (PH == 0) ? 512 : (PH == 1) ? 128 : (PH == 2) ? 256 : 128;
    constexpr int NKC = K3 / 32;
    constexpr bool STATS = (PH >= 1);
    constexpr int OSUM = (PH == 1) ? 0 : (PH == 2) ? 256 : 768;
    constexpr int OSQ  = (PH == 1) ? 128 : (PH == 2) ? 512 : 896;
    constexpr int WN   = (PH == 0 || PH == 2) ? 64 : 32;   // warp N width
    constexpr int CN   = WN * 2;                           // CTA N width
    constexpr int NB   = WN / 8;                           // n8 frags per k16
    constexpr int NF   = WN / 16;                          // ldsm.x4 per k16
    constexpr int BST  = CN * 64;                          // B stage bytes
    constexpr int NSUB = CN / 64;                          // B 64-col sub-tiles

    const __nv_bfloat16* Am = (PH == 0) ? g_A0 : (PH == 1) ? g_A1 : (PH == 2) ? g_A2 : g_A3;
    const __nv_bfloat16* Bm = (PH == 0) ? g_B0 : (PH == 1) ? g_B1 : (PH == 2) ? g_B2 : g_B3;
    float* Cm = (PH == 1) ? g_T1 : (PH == 2) ? g_U : g_T3;

    __shared__ __align__(128) char sbuf[NSTAGE * (4096 + BST)];
    __shared__ __align__(8) unsigned long long smbar[NSTAGE];
    __shared__ float s_emu[128];
    __shared__ float s_ers[128];

    int t = threadIdx.x;
    int lane = t & 31;
    int warp = t >> 5;
    int warpM = warp >> 1;
    int warpN = warp & 1;
    int r0 = blockIdx.x * 64;
    int c0 = blockIdx.y * CN;

    u32 sAu = (u32)__cvta_generic_to_shared(sbuf);
    u32 sBu = sAu + NSTAGE * 4096;
    u32 mb0 = (u32)__cvta_generic_to_shared(smbar);

    if (t == 0) {
#pragma unroll
        for (int s = 0; s < NSTAGE; s++) mbar_init(mb0 + s * 8, 1);
    }
    if (PH == 3 && t < 128) {
        float mu = g_stats[t] * (1.f / 8192.f);
        float var = g_stats[128 + t] * (1.f / 8192.f) - mu * mu;
        s_emu[t] = mu;
        s_ers[t] = rsqrtf(var + 1e-5f);
    }
    __syncthreads();

    const __nv_bfloat16* Atile = Am + (size_t)blockIdx.x * NKC * 2048;

    if (t == 0) {
#pragma unroll
        for (int s = 0; s < NSTAGE; s++) {
            mbar_expect(mb0 + s * 8, 4096 + BST);
            cpbulk(sAu + s * 4096, Atile + s * 2048, 4096, mb0 + s * 8);
#pragma unroll
            for (int sub = 0; sub < NSUB; sub++) {
                cpbulk(sBu + s * BST + sub * 4096,
                       Bm + ((size_t)(blockIdx.y * NSUB + sub) * NKC + s) * 2048,
                       4096, mb0 + s * 8);
            }
        }
    }

    float acc[2][NB][4] = {};

    int a_r = warpM * 32 + (lane & 15);
    int a_p0 = lane >> 4;
    // B: for CN=128, each warp owns one 4KB sub-tile (64 local rows); for CN=64, half of one tile
    int b_sub = (NSUB == 2) ? warpN : 0;
    int b_base = (NSUB == 2) ? 0 : warpN * 32;
    int b_r0 = b_base + (lane & 7) + ((lane >> 4) << 3);
    int b_p0 = (lane >> 3) & 1;

    for (int c = 0; c < NKC; c++) {
        int buf = c & (NSTAGE - 1);
        mbar_wait(mb0 + buf * 8, (c >> 2) & 1);
#pragma unroll
        for (int s = 0; s < 2; s++) {
            int k0p = s * 2;
            u32 af[2][4];
#pragma unroll
            for (int mt = 0; mt < 2; mt++) {
                int r = a_r + mt * 16;
                int p = k0p + a_p0;
                u32 addr = sAu + (u32)(buf * 4096 + r * 64 + ((p ^ ((r >> 1) & 3)) << 4));
                ldsm4(af[mt][0], af[mt][1], af[mt][2], af[mt][3], addr);
            }
            u32 bf[NB][2];
#pragma unroll
            for (int np = 0; np < NF; np++) {
                int r = b_r0 + np * 16;
                int p = k0p + b_p0;
                u32 addr = sBu + (u32)(buf * BST + b_sub * 4096 + r * 64 + ((p ^ ((r >> 1) & 3)) << 4));
                u32 q0, q1, q2, q3;
                ldsm4(q0, q1, q2, q3, addr);
                bf[np * 2][0] = q0;
                bf[np * 2][1] = q1;
                bf[np * 2 + 1][0] = q2;
                bf[np * 2 + 1][1] = q3;
            }
#pragma unroll
            for (int mt = 0; mt < 2; mt++) {
#pragma unroll
                for (int nt = 0; nt < NB; nt++) {
                    mma16816(acc[mt][nt], af[mt], bf[nt]);
                }
            }
        }
        __syncthreads();
        int cn = c + NSTAGE;
        if (t == 0 && cn < NKC) {
            mbar_expect(mb0 + buf * 8, 4096 + BST);
            cpbulk(sAu + buf * 4096, Atile + cn * 2048, 4096, mb0 + buf * 8);
#pragma unroll
            for (int sub = 0; sub < NSUB; sub++) {
                cpbulk(sBu + buf * BST + sub * 4096,
                       Bm + ((size_t)(blockIdx.y * NSUB + sub) * NKC + cn) * 2048,
                       4096, mb0 + buf * 8);
            }
        }
    }

    float colsum[2 * NB];
    float colsq[2 * NB];
#pragma unroll
    for (int i = 0; i < 2 * NB; i++) { colsum[i] = 0.f; colsq[i] = 0.f; }
#pragma unroll
    for (int mt = 0; mt < 2; mt++) {
        int m = r0 + warpM * 32 + mt * 16 + (lane >> 2);
#pragma unroll
        for (int nt = 0; nt < NB; nt++) {
            int cc = c0 + warpN * WN + nt * 8 + ((lane & 3) << 1);
            float v0 = acc[mt][nt][0];
            float v1 = acc[mt][nt][1];
            float v2 = acc[mt][nt][2];
            float v3 = acc[mt][nt][3];
            if (PH == 0) {
                if (cc < 512) {
                    __nv_bfloat162 p0;
                    p0.x = __float2bfloat16(v0);
                    p0.y = __float2bfloat16(v1);
                    *(__nv_bfloat162*)&g_Whb[(size_t)m * 512 + cc] = p0;
                    __nv_bfloat162 p1;
                    p1.x = __float2bfloat16(v2);
                    p1.y = __float2bfloat16(v3);
                    *(__nv_bfloat162*)&g_Whb[(size_t)(m + 8) * 512 + cc] = p1;
                } else {
                    int j = cc - 512;
                    if (j < 16) {
                        g_qv[(size_t)m * 16 + j] = v0;
                        g_qv[(size_t)m * 16 + j + 1] = v1;
                        g_qv[(size_t)(m + 8) * 16 + j] = v2;
                        g_qv[(size_t)(m + 8) * 16 + j + 1] = v3;
                    }
                }
            } else {
                if (PH == 1) {
                    float2 x0 = *(const float2*)&ext_x[(size_t)m * FD + cc];
                    float2 x1 = *(const float2*)&ext_x[(size_t)(m + 8) * FD + cc];
                    v0 = 0.5f * fmaxf(v0, 0.f) + 0.5f * x0.x;
                    v1 = 0.5f * fmaxf(v1, 0.f) + 0.5f * x0.y;
                    v2 = 0.5f * fmaxf(v2, 0.f) + 0.5f * x1.x;
                    v3 = 0.5f * fmaxf(v3, 0.f) + 0.5f * x1.y;
                }
                if (PH == 3) {
                    float2 t0 = *(const float2*)&g_T1[(size_t)m * FD + cc];
                    float2 t1 = *(const float2*)&g_T1[(size_t)(m + 8) * FD + cc];
                    v0 += (t0.x - s_emu[cc]) * s_ers[cc];
                    v1 += (t0.y - s_emu[cc + 1]) * s_ers[cc + 1];
                    v2 += (t1.x - s_emu[cc]) * s_ers[cc];
                    v3 += (t1.y - s_emu[cc + 1]) * s_ers[cc + 1];
                }
                *(float2*)&Cm[(size_t)m * NC + cc] = make_float2(v0, v1);
                *(float2*)&Cm[(size_t)(m + 8) * NC + cc] = make_float2(v2, v3);
                colsum[nt * 2] += v0 + v2;
                colsq[nt * 2] += v0 * v0 + v2 * v2;
                colsum[nt * 2 + 1] += v1 + v3;
                colsq[nt * 2 + 1] += v1 * v1 + v3 * v3;
            }
        }
    }
    if (STATS) {
#pragma unroll
        for (int s2 = 0; s2 < 2 * NB; s2++) {
#pragma unroll
            for (int off = 4; off < 32; off <<= 1) {
                colsum[s2] += __shfl_xor_sync(0xffffffffu, colsum[s2], off);
                colsq[s2]  += __shfl_xor_sync(0xffffffffu, colsq[s2], off);
            }
        }
        if (lane < 4) {
#pragma unroll
            for (int nt = 0; nt < NB; nt++) {
#pragma unroll
                for (int p = 0; p < 2; p++) {
                    int col = c0 + warpN * WN + nt * 8 + lane * 2 + p;
                    atomicAdd(&g_stats[OSUM + col], colsum[nt * 2 + p]);
                    atomicAdd(&g_stats[OSQ + col], colsq[nt * 2 + p]);
                }
            }
        }
    }
}

// ---------------- sparse attention: one block per (bn, e) ----------------
__global__ __launch_bounds__(256) void k_attn() {
    __shared__ unsigned short s_m[ECAP];
    __shared__ int s_um[ECAP];
    __shared__ float s_uc[ECAP];
    __shared__ float s_w[ECAP][4];
    __shared__ int s_cnt;
    int bn = blockIdx.x >> 1;
    int e = blockIdx.x & 1;
    int b = bn >> 10;
    int n = bn & 1023;
    int t = threadIdx.x;
    int h = t >> 6;
    int g = t & 63;
    int r = (b * EC + e) * 1024 + n;
    int len = (int)g_deg[r];
    if (len > ECAP) len = ECAP;
    if (t == 0) s_cnt = 0;
    if (t < len) s_m[t] = g_edges2[(size_t)r * ECAP + t];
    __syncthreads();
    if (t < len) {
        int m = s_m[t];
        int c = 0;
        bool own = true;
        for (int i2 = 0; i2 < len; i2++) {
            int mi = s_m[i2];
            if (mi == m) {
                c++;
                if (i2 < t) own = false;
            }
        }
        if (own) {
            int slot = atomicAdd(&s_cnt, 1);
            s_um[slot] = m;
            s_uc[slot] = (float)c;
        }
    }
    __syncthreads();
    int cnt = s_cnt;
    if (t < cnt * 4) {
        int j = t >> 2;
        int hh = t & 3;
        float qn = g_qv[(size_t)bn * 16 + e * 4 + hh];
        float vm = g_qv[((size_t)b * NNODE + s_um[j]) * 16 + 8 + e * 4 + hh];
        float s = qn * vm * s_uc[j];
        float l = s >= 0.f ? s : 0.01f * s;
        s_w[j][hh] = expf(l) - 1.f;
    }
    __syncthreads();
    const __nv_bfloat16* Whb = g_Whb + (size_t)b * NNODE * 512 + e * 256 + h * 64 + g;
    float num = 0.f;
    float den = 0.f;
    for (int j = 0; j < cnt; j++) {
        float w = s_w[j][h];
        num += w * __bfloat162float(__ldg(&Whb[(size_t)s_um[j] * 512]));
        den += w;
    }
    float outv = (g_Swh[b * 512 + e * 256 + h * 64 + g] + num) / (1024.f + den);
    int col = h * 128 + e * 64 + g;
    __nv_bfloat16 hi, lo;
    split2(outv, hi, lo);
    g_A1[tidx(bn, col, 48)] = hi;
    g_A1[tidx(bn, 512 + col, 48)] = hi;
    g_A1[tidx(bn, 1024 + col, 48)] = lo;
}

// ---------------- final normalization ----------------
__global__ void k_norm3(float* __restrict__ out) {
    int i = blockIdx.x * blockDim.x + threadIdx.x;
    int col = i & 127;
    float mu = g_stats[768 + col] * (1.f / 8192.f);
    float var = g_stats[896 + col] * (1.f / 8192.f) - mu * mu;
    float rs = rsqrtf(var + 1e-5f);
    out[i] = (g_T3[i] - mu) * rs;
}

// ---------------- launch ----------------
extern "C" void kernel_launch(void* const* d_in, const int* in_sizes, int n_in,
                              void* d_out, int out_size) {
    const int*   A    = (const int*)d_in[0];
    const float* X    = (const float*)d_in[1];
    const float* Ws   = (const float*)d_in[2];
    const float* Wq   = (const float*)d_in[3];
    const float* Wv   = (const float*)d_in[4];
    const float* Wemb = (const float*)d_in[5];
    const float* Wl0  = (const float*)d_in[6];
    const float* Wl1  = (const float*)d_in[7];
    float* out = (float*)d_out;

    k_packb<<<1104, 256>>>(Ws, Wemb, Wl0, Wl1, Wq, Wv);
    k_bucket<<<512, 512>>>(A);
    k_conv0<<<512, 256>>>(X);
    k_mma<0><<<dim3(128, 5), 128>>>(nullptr);      // Whb (bf16) + qv, CN=128
    k_swh<<<dim3(8, 4), 128>>>();
    k_attn<<<16384, 256>>>();
    k_mma<1><<<dim3(128, 2), 128>>>(X);            // T1 + stats, CN=64
    k_conv<2><<<4096, 256>>>();
    k_mma<2><<<dim3(128, 2), 128>>>(nullptr);      // U + stats, CN=128
    k_conv<3><<<8192, 256>>>();
    k_mma<3><<<dim3(128, 2), 128>>>(nullptr);      // T3 + stats, CN=64
    k_norm3<<<4096, 256>>>(out);
}

// round 16
// speedup vs baseline: 1.0690x; 1.0690x over previous
#include <cuda_runtime.h>
#include <cuda_bf16.h>
#include <cstdint>
#include <math.h>

typedef unsigned int u32;

#define BB 8
#define NNODE 1024
#define FD 128
#define GD 64
#define EC 2
#define NH 4
#define NEDGE 16384
#define L0D 256
#define ROWS (BB*NNODE)
#define ECAP 64

// ---------------- scratch ----------------
__device__ u32 g_deg[16*1024];                 // zeroed by norm3 tail each call (starts zero)
__device__ unsigned short g_edges2[16*1024*ECAP];
__device__ __align__(4) __nv_bfloat16 g_Whb[(size_t)ROWS*512];
__device__ float g_qv[ROWS*16];
__device__ float g_W2[512*128];
__device__ float g_XsumP[512*128];             // per-conv0-block partials (overwritten each call)
__device__ float g_Swh[BB*512];
__device__ float g_T1[ROWS*FD];
__device__ float g_U[ROWS*L0D];
__device__ float g_T3[ROWS*FD];
__device__ float g_stats[1024];                // zeroed in k_setup each call
// split-bf16 A matrices [Ahi | Ahi | Alo] along K, tile-chunk-contiguous swizzled layout
__device__ __align__(16) __nv_bfloat16 g_A0[(size_t)ROWS*384];
__device__ __align__(16) __nv_bfloat16 g_A1[(size_t)ROWS*1536];
__device__ __align__(16) __nv_bfloat16 g_A2[(size_t)ROWS*384];
__device__ __align__(16) __nv_bfloat16 g_A3[(size_t)ROWS*768];
// split-bf16 B matrices [Bhi | Blo | Bhi] along K, same tiled layout
__device__ __align__(16) __nv_bfloat16 g_B0[640*384];
__device__ __align__(16) __nv_bfloat16 g_B1[128*1536];
__device__ __align__(16) __nv_bfloat16 g_B2[256*384];
__device__ __align__(16) __nv_bfloat16 g_B3[128*768];

// tiled index: tile = row>>6, chunk = k>>5; within tile: 64 rows x 32 halves,
// 16B part swizzled by p ^ ((r>>1)&3) for conflict-free ldmatrix
__device__ __forceinline__ size_t tidx(int row, int k, int nkc) {
    int rt = row >> 6;
    int r = row & 63;
    int ch = k >> 5;
    int kc = k & 31;
    int ps = (kc >> 3) ^ ((r >> 1) & 3);
    return ((size_t)(rt * nkc + ch) * 64 + r) * 32 + ps * 8 + (kc & 7);
}

// ---------------- asm helpers ----------------
__device__ __forceinline__ void cpbulk(u32 dst, const void* src, u32 bytes, u32 mbar) {
    asm volatile("cp.async.bulk.shared::cluster.global.mbarrier::complete_tx::bytes [%0], [%1], %2, [%3];\n"
                 :: "r"(dst), "l"(src), "r"(bytes), "r"(mbar) : "memory");
}
__device__ __forceinline__ void mbar_init(u32 mbar, u32 cnt) {
    asm volatile("mbarrier.init.shared.b64 [%0], %1;\n" :: "r"(mbar), "r"(cnt) : "memory");
}
__device__ __forceinline__ void mbar_expect(u32 mbar, u32 bytes) {
    asm volatile("mbarrier.arrive.expect_tx.shared.b64 _, [%0], %1;\n" :: "r"(mbar), "r"(bytes) : "memory");
}
__device__ __forceinline__ void mbar_wait(u32 mbar, u32 parity) {
    asm volatile(
        "{\n\t"
        ".reg .pred P1;\n\t"
        "WAIT_LOOP_%=:\n\t"
        "mbarrier.try_wait.parity.acquire.cta.shared::cta.b64 P1, [%0], %1, 0x989680;\n\t"
        "@P1 bra.uni WAIT_DONE_%=;\n\t"
        "bra.uni WAIT_LOOP_%=;\n\t"
        "WAIT_DONE_%=:\n\t"
        "}"
        :: "r"(mbar), "r"(parity) : "memory");
}
__device__ __forceinline__ void ldsm4(u32& r0, u32& r1, u32& r2, u32& r3, u32 a) {
    asm volatile("ldmatrix.sync.aligned.m8n8.x4.shared.b16 {%0,%1,%2,%3}, [%4];\n"
                 : "=r"(r0), "=r"(r1), "=r"(r2), "=r"(r3) : "r"(a));
}
__device__ __forceinline__ void mma16816(float* d, const u32* a, const u32* b) {
    asm volatile("mma.sync.aligned.m16n8k16.row.col.f32.bf16.bf16.f32 "
                 "{%0,%1,%2,%3},{%4,%5,%6,%7},{%8,%9},{%0,%1,%2,%3};\n"
                 : "+f"(d[0]), "+f"(d[1]), "+f"(d[2]), "+f"(d[3])
                 : "r"(a[0]), "r"(a[1]), "r"(a[2]), "r"(a[3]), "r"(b[0]), "r"(b[1]));
}
__device__ __forceinline__ void split2(float x, __nv_bfloat16& hi, __nv_bfloat16& lo) {
    hi = __float2bfloat16(x);
    lo = __float2bfloat16(x - __bfloat162float(hi));
}

// ---------------- fused setup: packb + bucket + conv0 ----------------
// grid 2572 x 256: [0,1036) packb+stats-zero, [1036,2060) bucket, [2060,2572) conv0
__global__ __launch_bounds__(256) void k_setup(const int* __restrict__ A,
                                               const float* __restrict__ X,
                                               const float* __restrict__ Ws,
                                               const float* __restrict__ Wemb,
                                               const float* __restrict__ Wl0,
                                               const float* __restrict__ Wl1,
                                               const float* __restrict__ Wq,
                                               const float* __restrict__ Wv) {
    __shared__ float sh[256];
    int bid = blockIdx.x;
    int t = threadIdx.x;
    if (bid < 1036) {
        int idx = bid * 256 + t;
        __nv_bfloat16 hi, lo;
        if (idx < 65536) {                       // B0 main: cols 0..511 (nkc 12)
            int col = idx >> 7;
            int f = idx & 127;
            int e = col >> 8;
            int rem = col & 255;
            int h = rem >> 6;
            int g = rem & 63;
            split2(Ws[((size_t)e * 512 + h * 128 + f) * GD + g], hi, lo);
            g_B0[tidx(col, f, 12)] = hi;
            g_B0[tidx(col, 128 + f, 12)] = lo;
            g_B0[tidx(col, 256 + f, 12)] = hi;
        } else if (idx < 131072) {               // B1: 128 cols (nkc 48)
            int i2 = idx - 65536;
            int col = i2 >> 9;
            int k = i2 & 511;
            split2(Wemb[col * 512 + k], hi, lo);
            g_B1[tidx(col, k, 48)] = hi;
            g_B1[tidx(col, 512 + k, 48)] = lo;
            g_B1[tidx(col, 1024 + k, 48)] = hi;
        } else if (idx < 163840) {               // B2: 256 cols (nkc 12)
            int i2 = idx - 131072;
            int col = i2 >> 7;
            int k = i2 & 127;
            split2(Wl0[col * 128 + k], hi, lo);
            g_B2[tidx(col, k, 12)] = hi;
            g_B2[tidx(col, 128 + k, 12)] = lo;
            g_B2[tidx(col, 256 + k, 12)] = hi;
        } else if (idx < 196608) {               // B3: 128 cols (nkc 24)
            int i2 = idx - 163840;
            int col = i2 >> 8;
            int k = i2 & 255;
            split2(Wl1[col * 256 + k], hi, lo);
            g_B3[tidx(col, k, 24)] = hi;
            g_B3[tidx(col, 256 + k, 24)] = lo;
            g_B3[tidx(col, 512 + k, 24)] = hi;
        } else if (idx < 198656) {               // B0 qv rows: cols 512..527
            int i2 = idx - 196608;
            int j = i2 >> 7;
            int f = i2 & 127;
            int col = 512 + j;
            float w;
            if (j < 8) w = Wq[(j >> 2) * 512 + (j & 3) * 128 + f];
            else {
                int c = j - 8;
                w = Wv[(c >> 2) * 512 + (c & 3) * 128 + f];
            }
            split2(w, hi, lo);
            g_B0[tidx(col, f, 12)] = hi;
            g_B0[tidx(col, 128 + f, 12)] = lo;
            g_B0[tidx(col, 256 + f, 12)] = hi;
        } else if (idx < 264192) {               // W2 fp32: 512 x 128 (for Swh)
            int i2 = idx - 198656;
            int col = i2 >> 7;
            int f = i2 & 127;
            int e = col >> 8;
            int rem = col & 255;
            int h = rem >> 6;
            int g = rem & 63;
            g_W2[i2] = Ws[((size_t)e * 512 + h * 128 + f) * GD + g];
        } else if (idx < 265216) {               // zero g_stats
            g_stats[idx - 264192] = 0.f;
        }
    } else if (bid < 2060) {                     // bucket (g_deg pre-zeroed by previous call)
        int idx = (bid - 1036) * 256 + t;
        int be = idx >> 14;
        int i = idx & (NEDGE - 1);
        int src = A[(be * 2 + 0) * NEDGE + i];
        int dst = A[(be * 2 + 1) * NEDGE + i];
        int row = be * 1024 + src;
        u32 pos = atomicAdd(&g_deg[row], 1u);
        if (pos < ECAP) g_edges2[(size_t)row * ECAP + pos] = (unsigned short)dst;
    } else {                                     // conv0: X -> A0 split + partial column sums
        int cb = bid - 2060;
        int row0 = cb * 16;
        int f = t & 127;
        int rl = t >> 7;
        float s = 0.f;
        for (int r = rl; r < 16; r += 2) {
            int row = row0 + r;
            float x = X[(size_t)row * FD + f];
            s += x;
            __nv_bfloat16 hi, lo;
            split2(x, hi, lo);
            g_A0[tidx(row, f, 12)] = hi;
            g_A0[tidx(row, 128 + f, 12)] = hi;
            g_A0[tidx(row, 256 + f, 12)] = lo;
        }
        sh[t] = s;
        __syncthreads();
        if (t < 128) g_XsumP[cb * 128 + t] = sh[t] + sh[t + 128];
    }
}

// Swh block (fused into k_mma<0> tail blocks): Swh[b][col] = sum_f Xsum[b][f]*W2[col][f]
__device__ void swh_block(int sbid, float* sx) {
    int t = threadIdx.x;          // 128 threads
    int b = sbid >> 2;
    int cq = sbid & 3;
    float s = 0.f;
    for (int p = 0; p < 64; p++) s += g_XsumP[((b << 6) + p) * 128 + t];
    sx[t] = s;
    __syncthreads();
    int col = cq * 128 + t;
    float acc = 0.f;
#pragma unroll 4
    for (int f = 0; f < 128; f++) acc += sx[f] * g_W2[col * 128 + f];
    g_Swh[b * 512 + col] = acc;
}

// bn conversions: PH2 bn(T1)->A2 (nkc 12), PH3 elu(bn(U))->A3 (nkc 24)
template <int PH>
__global__ void k_conv() {
    constexpr int C = (PH == 3) ? 256 : 128;
    constexpr int NKC = (PH == 3) ? 24 : 12;
    int idx = blockIdx.x * blockDim.x + threadIdx.x;
    int row = idx / C;
    int k = idx % C;
    constexpr int SO = (PH == 2) ? 0 : 256;
    constexpr int QO = (PH == 2) ? 128 : 512;
    const float* src = (PH == 2) ? g_T1 : g_U;
    float mu = g_stats[SO + k] * (1.f / 8192.f);
    float var = g_stats[QO + k] * (1.f / 8192.f) - mu * mu;
    float x = (src[idx] - mu) * rsqrtf(var + 1e-5f);
    if (PH == 3) x = x > 0.f ? x : expm1f(x);
    __nv_bfloat16 hi, lo;
    split2(x, hi, lo);
    __nv_bfloat16* a = (PH == 2) ? g_A2 : g_A3;
    a[tidx(row, k, NKC)] = hi;
    a[tidx(row, C + k, NKC)] = hi;
    a[tidx(row, 2 * C + k, NKC)] = lo;
}

// ---------------- tensor-core GEMM: 64x64 tiles, bulk-copy pipeline ----------------
template <int PH>
__global__ __launch_bounds__(128) void k_mma(const float* __restrict__ ext_x) {
    constexpr int K3 = (PH == 0) ? 384 : (PH == 1) ? 1536 : (PH == 2) ? 384 : 768;
    constexpr int NC = (PH == 0) ? 512 : (PH == 1) ? 128 : (PH == 2) ? 256 : 128;
    constexpr int NKC = K3 / 32;
    constexpr int NST = (PH == 1 || PH == 3) ? 6 : 4;
    constexpr bool STATS = (PH >= 1);
    constexpr int OSUM = (PH == 1) ? 0 : (PH == 2) ? 256 : 768;
    constexpr int OSQ  = (PH == 1) ? 128 : (PH == 2) ? 512 : 896;

    const __nv_bfloat16* Am = (PH == 0) ? g_A0 : (PH == 1) ? g_A1 : (PH == 2) ? g_A2 : g_A3;
    const __nv_bfloat16* Bm = (PH == 0) ? g_B0 : (PH == 1) ? g_B1 : (PH == 2) ? g_B2 : g_B3;
    float* Cm = (PH == 1) ? g_T1 : (PH == 2) ? g_U : g_T3;

    __shared__ __align__(128) char sbuf[NST * 8192];      // NST x (A 4KB + B 4KB)
    __shared__ __align__(8) unsigned long long smbar[NST];
    __shared__ float s_emu[128];
    __shared__ float s_ers[128];

    int bidm, bidn;
    if (PH == 0) {
        if (blockIdx.x >= 1280) {          // fused Swh blocks
            swh_block(blockIdx.x - 1280, s_emu);
            return;
        }
        bidm = blockIdx.x & 127;
        bidn = blockIdx.x >> 7;
    } else {
        bidm = blockIdx.x;
        bidn = blockIdx.y;
    }

    int t = threadIdx.x;
    int lane = t & 31;
    int warp = t >> 5;
    int warpM = warp >> 1;
    int warpN = warp & 1;
    int r0 = bidm * 64;
    int c0 = bidn * 64;

    u32 sAu = (u32)__cvta_generic_to_shared(sbuf);
    u32 sBu = sAu + NST * 4096;
    u32 mb0 = (u32)__cvta_generic_to_shared(smbar);

    if (t == 0) {
#pragma unroll
        for (int s = 0; s < NST; s++) mbar_init(mb0 + s * 8, 1);
    }
    if (PH == 3 && t < 128) {
        float mu = g_stats[t] * (1.f / 8192.f);
        float var = g_stats[128 + t] * (1.f / 8192.f) - mu * mu;
        s_emu[t] = mu;
        s_ers[t] = rsqrtf(var + 1e-5f);
    }
    __syncthreads();

    const __nv_bfloat16* Atile = Am + (size_t)bidm * NKC * 2048;
    const __nv_bfloat16* Btile = Bm + (size_t)bidn * NKC * 2048;

    if (t == 0) {
#pragma unroll
        for (int s = 0; s < NST; s++) {
            mbar_expect(mb0 + s * 8, 8192);
            cpbulk(sAu + s * 4096, Atile + s * 2048, 4096, mb0 + s * 8);
            cpbulk(sBu + s * 4096, Btile + s * 2048, 4096, mb0 + s * 8);
        }
    }

    float acc[2][4][4] = {};

    int a_r = warpM * 32 + (lane & 15);
    int a_p0 = lane >> 4;
    int b_r0 = warpN * 32 + (lane & 7) + ((lane >> 4) << 3);
    int b_p0 = (lane >> 3) & 1;

    for (int c = 0; c < NKC; c++) {
        int buf = c % NST;
        mbar_wait(mb0 + buf * 8, (c / NST) & 1);
#pragma unroll
        for (int s = 0; s < 2; s++) {
            int k0p = s * 2;
            u32 af[2][4];
#pragma unroll
            for (int mt = 0; mt < 2; mt++) {
                int r = a_r + mt * 16;
                int p = k0p + a_p0;
                u32 addr = sAu + (u32)(buf * 4096 + r * 64 + ((p ^ ((r >> 1) & 3)) << 4));
                ldsm4(af[mt][0], af[mt][1], af[mt][2], af[mt][3], addr);
            }
            u32 bf[4][2];
#pragma unroll
            for (int np = 0; np < 2; np++) {
                int r = b_r0 + np * 16;
                int p = k0p + b_p0;
                u32 addr = sBu + (u32)(buf * 4096 + r * 64 + ((p ^ ((r >> 1) & 3)) << 4));
                u32 q0, q1, q2, q3;
                ldsm4(q0, q1, q2, q3, addr);
                bf[np * 2][0] = q0;
                bf[np * 2][1] = q1;
                bf[np * 2 + 1][0] = q2;
                bf[np * 2 + 1][1] = q3;
            }
#pragma unroll
            for (int mt = 0; mt < 2; mt++) {
#pragma unroll
                for (int nt = 0; nt < 4; nt++) {
                    mma16816(acc[mt][nt], af[mt], bf[nt]);
                }
            }
        }
        __syncthreads();
        int cn = c + NST;
        if (t == 0 && cn < NKC) {
            mbar_expect(mb0 + buf * 8, 8192);
            cpbulk(sAu + buf * 4096, Atile + cn * 2048, 4096, mb0 + buf * 8);
            cpbulk(sBu + buf * 4096, Btile + cn * 2048, 4096, mb0 + buf * 8);
        }
    }

    float colsum[8] = {0.f, 0.f, 0.f, 0.f, 0.f, 0.f, 0.f, 0.f};
    float colsq[8]  = {0.f, 0.f, 0.f, 0.f, 0.f, 0.f, 0.f, 0.f};
#pragma unroll
    for (int mt = 0; mt < 2; mt++) {
        int m = r0 + warpM * 32 + mt * 16 + (lane >> 2);
#pragma unroll
        for (int nt = 0; nt < 4; nt++) {
            int cc = c0 + warpN * 32 + nt * 8 + ((lane & 3) << 1);
            float v0 = acc[mt][nt][0];
            float v1 = acc[mt][nt][1];
            float v2 = acc[mt][nt][2];
            float v3 = acc[mt][nt][3];
            if (PH == 0) {
                if (cc < 512) {
                    __nv_bfloat162 p0;
                    p0.x = __float2bfloat16(v0);
                    p0.y = __float2bfloat16(v1);
                    *(__nv_bfloat162*)&g_Whb[(size_t)m * 512 + cc] = p0;
                    __nv_bfloat162 p1;
                    p1.x = __float2bfloat16(v2);
                    p1.y = __float2bfloat16(v3);
                    *(__nv_bfloat162*)&g_Whb[(size_t)(m + 8) * 512 + cc] = p1;
                } else {
                    int j = cc - 512;
                    if (j < 16) {
                        g_qv[(size_t)m * 16 + j] = v0;
                        g_qv[(size_t)m * 16 + j + 1] = v1;
                        g_qv[(size_t)(m + 8) * 16 + j] = v2;
                        g_qv[(size_t)(m + 8) * 16 + j + 1] = v3;
                    }
                }
            } else {
                if (PH == 1) {
                    float2 x0 = *(const float2*)&ext_x[(size_t)m * FD + cc];
                    float2 x1 = *(const float2*)&ext_x[(size_t)(m + 8) * FD + cc];
                    v0 = 0.5f * fmaxf(v0, 0.f) + 0.5f * x0.x;
                    v1 = 0.5f * fmaxf(v1, 0.f) + 0.5f * x0.y;
                    v2 = 0.5f * fmaxf(v2, 0.f) + 0.5f * x1.x;
                    v3 = 0.5f * fmaxf(v3, 0.f) + 0.5f * x1.y;
                }
                if (PH == 3) {
                    float2 t0 = *(const float2*)&g_T1[(size_t)m * FD + cc];
                    float2 t1 = *(const float2*)&g_T1[(size_t)(m + 8) * FD + cc];
                    v0 += (t0.x - s_emu[cc]) * s_ers[cc];
                    v1 += (t0.y - s_emu[cc + 1]) * s_ers[cc + 1];
                    v2 += (t1.x - s_emu[cc]) * s_ers[cc];
                    v3 += (t1.y - s_emu[cc + 1]) * s_ers[cc + 1];
                }
                *(float2*)&Cm[(size_t)m * NC + cc] = make_float2(v0, v1);
                *(float2*)&Cm[(size_t)(m + 8) * NC + cc] = make_float2(v2, v3);
                colsum[nt * 2] += v0 + v2;
                colsq[nt * 2] += v0 * v0 + v2 * v2;
                colsum[nt * 2 + 1] += v1 + v3;
                colsq[nt * 2 + 1] += v1 * v1 + v3 * v3;
            }
        }
    }
    if (STATS) {
#pragma unroll
        for (int s2 = 0; s2 < 8; s2++) {
#pragma unroll
            for (int off = 4; off < 32; off <<= 1) {
                colsum[s2] += __shfl_xor_sync(0xffffffffu, colsum[s2], off);
                colsq[s2]  += __shfl_xor_sync(0xffffffffu, colsq[s2], off);
            }
        }
        if (lane < 4) {
#pragma unroll
            for (int nt = 0; nt < 4; nt++) {
#pragma unroll
                for (int p = 0; p < 2; p++) {
                    int col = c0 + warpN * 32 + nt * 8 + lane * 2 + p;
                    atomicAdd(&g_stats[OSUM + col], colsum[nt * 2 + p]);
                    atomicAdd(&g_stats[OSQ + col], colsq[nt * 2 + p]);
                }
            }
        }
    }
}

// ---------------- sparse attention: one block per (bn, e) ----------------
__global__ __launch_bounds__(256) void k_attn() {
    __shared__ unsigned short s_m[ECAP];
    __shared__ int s_um[ECAP];
    __shared__ float s_uc[ECAP];
    __shared__ float s_w[ECAP][4];
    __shared__ int s_cnt;
    int bn = blockIdx.x >> 1;
    int e = blockIdx.x & 1;
    int b = bn >> 10;
    int n = bn & 1023;
    int t = threadIdx.x;
    int h = t >> 6;
    int g = t & 63;
    int r = (b * EC + e) * 1024 + n;
    int len = (int)g_deg[r];
    if (len > ECAP) len = ECAP;
    if (t == 0) s_cnt = 0;
    if (t < len) s_m[t] = g_edges2[(size_t)r * ECAP + t];
    __syncthreads();
    if (t < len) {
        int m = s_m[t];
        int c = 0;
        bool own = true;
        for (int i2 = 0; i2 < len; i2++) {
            int mi = s_m[i2];
            if (mi == m) {
                c++;
                if (i2 < t) own = false;
            }
        }
        if (own) {
            int slot = atomicAdd(&s_cnt, 1);
            s_um[slot] = m;
            s_uc[slot] = (float)c;
        }
    }
    __syncthreads();
    int cnt = s_cnt;
    if (t < cnt * 4) {
        int j = t >> 2;
        int hh = t & 3;
        float qn = g_qv[(size_t)bn * 16 + e * 4 + hh];
        float vm = g_qv[((size_t)b * NNODE + s_um[j]) * 16 + 8 + e * 4 + hh];
        float s = qn * vm * s_uc[j];
        float l = s >= 0.f ? s : 0.01f * s;
        s_w[j][hh] = expf(l) - 1.f;
    }
    __syncthreads();
    const __nv_bfloat16* Whb = g_Whb + (size_t)b * NNODE * 512 + e * 256 + h * 64 + g;
    float num = 0.f;
    float den = 0.f;
    for (int j = 0; j < cnt; j++) {
        float w = s_w[j][h];
        num += w * __bfloat162float(__ldg(&Whb[(size_t)s_um[j] * 512]));
        den += w;
    }
    float outv = (g_Swh[b * 512 + e * 256 + h * 64 + g] + num) / (1024.f + den);
    int col = h * 128 + e * 64 + g;
    __nv_bfloat16 hi, lo;
    split2(outv, hi, lo);
    g_A1[tidx(bn, col, 48)] = hi;
    g_A1[tidx(bn, 512 + col, 48)] = hi;
    g_A1[tidx(bn, 1024 + col, 48)] = lo;
}

// ---------------- final normalization + deg re-zero ----------------
__global__ void k_norm3(float* __restrict__ out) {
    if (blockIdx.x >= 4096) {
        int i = (blockIdx.x - 4096) * blockDim.x + threadIdx.x;
        if (i < 16384) g_deg[i] = 0u;       // ready for next replay
        return;
    }
    int i = blockIdx.x * blockDim.x + threadIdx.x;
    int col = i & 127;
    float mu = g_stats[768 + col] * (1.f / 8192.f);
    float var = g_stats[896 + col] * (1.f / 8192.f) - mu * mu;
    float rs = rsqrtf(var + 1e-5f);
    out[i] = (g_T3[i] - mu) * rs;
}

// ---------------- launch ----------------
extern "C" void kernel_launch(void* const* d_in, const int* in_sizes, int n_in,
                              void* d_out, int out_size) {
    const int*   A    = (const int*)d_in[0];
    const float* X    = (const float*)d_in[1];
    const float* Ws   = (const float*)d_in[2];
    const float* Wq   = (const float*)d_in[3];
    const float* Wv   = (const float*)d_in[4];
    const float* Wemb = (const float*)d_in[5];
    const float* Wl0  = (const float*)d_in[6];
    const float* Wl1  = (const float*)d_in[7];
    float* out = (float*)d_out;

    k_setup<<<2572, 256>>>(A, X, Ws, Wemb, Wl0, Wl1, Wq, Wv);
    k_mma<0><<<1312, 128>>>(nullptr);              // Whb + qv (blocks 0..1279) + Swh (1280..1311)
    k_attn<<<16384, 256>>>();
    k_mma<1><<<dim3(128, 2), 128>>>(X);            // T1 + stats
    k_conv<2><<<4096, 256>>>();
    k_mma<2><<<dim3(128, 4), 128>>>(nullptr);      // U + stats
    k_conv<3><<<8192, 256>>>();
    k_mma<3><<<dim3(128, 2), 128>>>(nullptr);      // T3 + stats
    k_norm3<<<4160, 256>>>(out);
}